// round 9
// baseline (speedup 1.0000x reference)
#include <cuda_runtime.h>
#include <math.h>

#define NSAMP  24000
#define CH     8             // samples per lane
#define SPW    256           // samples per warp (32 * 8)
#define NCTA   8             // cluster size = grid size
#define NTHR   512           // 16 warps per CTA
#define WPC    16            // warps per CTA
#define CUTOFF 0.1f
#define OMC    0.9f          // 1 - CUTOFF
#define A8     0.43046721f   // 0.9^8
#define TSTEP  (1.0f / 23999.0f)

// Global scratch (device global: no allocation)
__device__ float g_trans[NSAMP];

__device__ __forceinline__ float tanh_fast(float x) {
    // exact identity tanh(x) = 1 - 2/(e^{2x}+1); saturates correctly at +-inf
    float e = __expf(2.0f * x);
    return 1.0f - __fdividef(2.0f, e + 1.0f);
}

__device__ __forceinline__ void cluster_sync() {
    asm volatile("barrier.cluster.arrive.aligned;" ::: "memory");   // release
    asm volatile("barrier.cluster.wait.aligned;"   ::: "memory");   // acquire
}

__global__ __launch_bounds__(NTHR, 1) __cluster_dims__(NCTA, 1, 1)
void drum_synth_cluster(const float* __restrict__ p,
                        const float* __restrict__ noise_t,
                        const float* __restrict__ noise_n,
                        float* __restrict__ out)
{
    extern __shared__ float sm[];      // str[24000] trans copy, sre[24000] resonator
    float* str = sm;
    float* sre = sm + NSAMP;
    __shared__ float sWB[WPC];         // per-warp chunk aggregates (carry exchange)

    const int tid  = threadIdx.x;
    const int lane = tid & 31;
    const int wl   = tid >> 5;                     // warp within CTA
    const int w    = blockIdx.x * WPC + wl;        // global warp 0..127

    const float decay_t  = p[1];
    const float freq_t   = p[2];
    const float sat      = p[3];
    const float gain_t   = p[4];
    const float freq_r   = p[5];
    const float feedback = p[6];
    const float gain_r   = p[7];
    const float attack_n = p[8];
    const float decay_n  = p[9];
    const float gain_n   = p[10];

    const int  s0  = w * SPW + lane * CH;
    const bool act = (s0 + CH <= NSAMP);
    const int  v0  = s0 >> 2;                       // float4 index
    const float4* ntv = (const float4*)noise_t;

    // ======== Phase A1: main chunk partials from y=0 (register-resident) ========
    float bk[CH];
    float ma = 1.0f, mb = 0.0f;
    if (act) {
        float4 x0 = ntv[v0], x1 = ntv[v0 + 1];
        float xs[CH] = {x0.x, x0.y, x0.z, x0.w, x1.x, x1.y, x1.z, x1.w};
        float y = 0.0f;
        #pragma unroll
        for (int s = 0; s < CH; ++s) { y = fmaf(OMC, y, CUTOFF * xs[s]); bk[s] = y; }
        mb = y; ma = A8;
    }
    // inclusive warp scan of affine pairs
    #pragma unroll
    for (int off = 1; off < 32; off <<= 1) {
        float au = __shfl_up_sync(0xffffffffu, ma, off);
        float bu = __shfl_up_sync(0xffffffffu, mb, off);
        if (lane >= off) { mb = fmaf(ma, bu, mb); ma *= au; }
    }
    float a_ie = __shfl_up_sync(0xffffffffu, ma, 1);
    float b_ie = __shfl_up_sync(0xffffffffu, mb, 1);
    if (lane == 0) { a_ie = 1.0f; b_ie = 0.0f; }
    if (lane == 31) sWB[wl] = mb;     // warp aggregate B (0.9^256 * older ~ 1e-12)

    // ======== Phase A2: cross-CTA halo — ONLY warp 0 of each CTA ========
    float haloB = 0.0f;
    if (wl == 0) {
        float ha = 1.0f, hb = 0.0f;
        const int hs0 = s0 - SPW;
        if (hs0 >= 0 && hs0 + CH <= NSAMP) {
            const int hv = hs0 >> 2;
            float4 x0 = ntv[hv], x1 = ntv[hv + 1];
            float y;
            y = CUTOFF * x0.x;
            y = fmaf(OMC, y, CUTOFF * x0.y);
            y = fmaf(OMC, y, CUTOFF * x0.z);
            y = fmaf(OMC, y, CUTOFF * x0.w);
            y = fmaf(OMC, y, CUTOFF * x1.x);
            y = fmaf(OMC, y, CUTOFF * x1.y);
            y = fmaf(OMC, y, CUTOFF * x1.z);
            y = fmaf(OMC, y, CUTOFF * x1.w);
            hb = y; ha = A8;
        }
        #pragma unroll
        for (int off = 1; off < 32; off <<= 1) {
            float au = __shfl_up_sync(0xffffffffu, ha, off);
            float bu = __shfl_up_sync(0xffffffffu, hb, off);
            if (lane >= off) { hb = fmaf(ha, bu, hb); ha *= au; }
        }
        haloB = __shfl_sync(0xffffffffu, hb, 31);
    }
    __syncthreads();                   // sWB visible
    const float y_warp = (wl == 0) ? haloB : sWB[wl - 1];
    const float y_in   = fmaf(a_ie, y_warp, b_ie);   // filter state entering lane chunk

    // ======== Phase A3: transient via spiral/geometric recurrences ========
    float tr[CH];
    if (act) {
        const float t0 = (float)s0 * TSTEP;
        const float wf = 6.2831853f * freq_t;
        float sn, cs;
        sincosf(wf * t0, &sn, &cs);                 // accurate start phase
        const float sd = __sinf(wf * TSTEP);        // tiny-arg step rotation
        const float cd = __cosf(wf * TSTEP);
        const float m1 = __expf(-decay_t * TSTEP);
        const float m2 = __expf(-20.0f * decay_t * TSTEP);
        const float cdm = cd * m1, sdm = sd * m1;   // rotation x decay fused
        const float K  = gain_t * sat;
        const float e1 = __expf(-decay_t * t0);
        float u = sn * e1 * K;                       // = sn*e1*gain*sat (tanh arg)
        float v = cs * e1 * K;
        float e2g = __expf(-20.0f * decay_t * t0) * (gain_t * 0.5f);
        float q   = OMC * y_in * e2g;                // = 0.9^{s+1} * y_in * e2g_s
        const float cq = OMC * m2;
        #pragma unroll
        for (int s = 0; s < CH; ++s) {
            float sq = tanh_fast(u);                 // saturated sine
            tr[s] = sq + fmaf(bk[s], e2g, q);        // + filtered-noise component
            float u2 = fmaf(u, cdm,  v * sdm);       // spiral step
            float v2 = fmaf(v, cdm, -u * sdm);
            u = u2; v = v2;
            e2g *= m2; q *= cq;
        }
        float4* tv = (float4*)g_trans;
        tv[v0]     = make_float4(tr[0], tr[1], tr[2], tr[3]);
        tv[v0 + 1] = make_float4(tr[4], tr[5], tr[6], tr[7]);
    }

    // ---- prefetch noise_n (cold) + envelope setup: overlaps sync + staging ----
    float4 nn0 = make_float4(0.f, 0.f, 0.f, 0.f), nn1 = nn0;
    if (act) { nn0 = ((const float4*)noise_n)[v0]; nn1 = ((const float4*)noise_n)[v0 + 1]; }
    const float t0c = (float)s0 * TSTEP;
    float eA = __expf(-attack_n * t0c);
    float eD = __expf(-decay_n  * t0c);
    const float a1 = __expf(-attack_n * TSTEP);
    const float d1 = __expf(-decay_n  * TSTEP);

    // cluster barrier: arrive=release orders g_trans stores; wait=acquire.
    cluster_sync();

    // ======== Phase B: resonator, REDUNDANT per CTA, chains run from smem ========
    // Stage g_trans -> local smem (coalesced float4 burst, high MLP)
    {
        const float4* tv = (const float4*)g_trans;
        float4*       sv = (float4*)str;
        #pragma unroll
        for (int j = 0; j < 12; ++j) {
            int i4 = tid + j * NTHR;
            if (i4 < NSAMP / 4) sv[i4] = tv[i4];
        }
    }

    const float D  = 48000.0f / freq_r;
    const int   Di = (int)D;
    const bool fastp = (D >= 1.0f) && ((float)Di == D) && (Di < NSAMP);

    if (fastp) {
        __syncthreads();
        // Integer delay: frac == 0 exactly -> Di independent chains, LDS-fed.
        for (int r = tid; r < Di; r += NTHR) {
            float yv = str[r];            // i < D => valid==0 => out = transient
            sre[r] = yv;
            #pragma unroll 5
            for (int i = r + Di; i < NSAMP; i += Di) {
                yv = fmaf(feedback, yv, str[i]);
                sre[i] = yv;
            }
        }
        __syncthreads();
    } else {
        // Generic fractional delay: wave-synchronous over zeroed smem res.
        for (int i = tid; i < NSAMP; i += NTHR) sre[i] = 0.0f;
        __syncthreads();
        if (tid == 0) sre[0] = str[0];
        int cD = (int)ceilf(D);
        int W  = min(max(cD - 1, 1), NTHR);
        __syncthreads();
        for (int b0 = 1; b0 < NSAMP; b0 += W) {
            const int i = b0 + tid;
            if (tid < W && i < NSAMP) {
                float delayed = (float)i - D;
                float valid   = (delayed >= 0.0f) ? 1.0f : 0.0f;
                int fl = min(max((int)floorf(delayed), 0), NSAMP - 1);
                int ce = min(fl + 1, NSAMP - 1);
                float frac = delayed - (float)fl;   // after clamp, as in reference
                float interp = (1.0f - frac) * sre[fl] + frac * sre[ce];
                sre[i] = str[i] + feedback * interp * valid;
            }
            __syncthreads();
        }
    }

    // ======== Phase C: noise envelope + final sum (tr in regs, res in smem) ====
    if (act) {
        const float4* rv = (const float4*)sre;
        float4 rs0 = rv[v0], rs1 = rv[v0 + 1];
        const float nnf[CH] = {nn0.x, nn0.y, nn0.z, nn0.w, nn1.x, nn1.y, nn1.z, nn1.w};
        const float rsf[CH] = {rs0.x, rs0.y, rs0.z, rs0.w, rs1.x, rs1.y, rs1.z, rs1.w};
        float o[CH];
        float eAk = eA, eDk = eD;
        #pragma unroll
        for (int s = 0; s < CH; ++s) {
            float env = (1.0f - eAk) * eDk;
            o[s] = fmaf(nnf[s] * gain_n, env, fmaf(rsf[s], gain_r, tr[s]));
            eAk *= a1; eDk *= d1;
        }
        float4* ov = (float4*)out;
        ov[v0]     = make_float4(o[0], o[1], o[2], o[3]);
        ov[v0 + 1] = make_float4(o[4], o[5], o[6], o[7]);
    }
}

extern "C" void kernel_launch(void* const* d_in, const int* in_sizes, int n_in,
                              void* d_out, int out_size)
{
    const float* params  = (const float*)d_in[0];
    const float* noise_t = (const float*)d_in[1];
    const float* noise_n = (const float*)d_in[2];
    float* out = (float*)d_out;

    const size_t smem_bytes = 2u * NSAMP * sizeof(float);   // 192000 B
    cudaFuncSetAttribute(drum_synth_cluster,
                         cudaFuncAttributeMaxDynamicSharedMemorySize,
                         (int)smem_bytes);

    drum_synth_cluster<<<NCTA, NTHR, smem_bytes>>>(params, noise_t, noise_n, out);
}

// round 10
// speedup vs baseline: 1.2143x; 1.2143x over previous
#include <cuda_runtime.h>
#include <math.h>

#define NSAMP  24000
#define CH     8             // samples per lane
#define SPW    256           // samples per warp (32 * 8)
#define NCTA   8             // cluster size = grid size
#define NTHR   512           // 16 warps per CTA
#define CUTOFF 0.1f
#define OMC    0.9f          // 1 - CUTOFF
#define A8     0.43046721f   // 0.9^8
#define TSTEP  (1.0f / 23999.0f)

// Global scratch (device global: no allocation)
__device__ float g_trans[NSAMP];

__device__ __forceinline__ float tanh_fast(float x) {
    // exact identity tanh(x) = 1 - 2/(e^{2x}+1); saturates correctly at +-inf
    float e = __expf(2.0f * x);
    return 1.0f - __fdividef(2.0f, e + 1.0f);
}

__device__ __forceinline__ void cluster_sync() {
    asm volatile("barrier.cluster.arrive.aligned;" ::: "memory");   // release
    asm volatile("barrier.cluster.wait.aligned;"   ::: "memory");   // acquire
}

__global__ __launch_bounds__(NTHR, 1) __cluster_dims__(NCTA, 1, 1)
void drum_synth_cluster(const float* __restrict__ p,
                        const float* __restrict__ noise_t,
                        const float* __restrict__ noise_n,
                        float* __restrict__ out)
{
    extern __shared__ float sm[];      // str[24000] trans copy, sre[24000] resonator
    float* str = sm;
    float* sre = sm + NSAMP;

    const int tid  = threadIdx.x;
    const int lane = tid & 31;
    const int w    = blockIdx.x * (NTHR / 32) + (tid >> 5);   // global warp 0..127

    const float decay_t  = p[1];
    const float freq_t   = p[2];
    const float sat      = p[3];
    const float gain_t   = p[4];
    const float freq_r   = p[5];
    const float feedback = p[6];
    const float gain_r   = p[7];
    const float attack_n = p[8];
    const float decay_n  = p[9];
    const float gain_n   = p[10];

    const int  s0  = w * SPW + lane * CH;
    const bool act = (s0 + CH <= NSAMP);
    const int  v0  = s0 >> 2;                       // float4 index
    const float4* ntv = (const float4*)noise_t;

    // ======== Phase A1: halo — redundantly reduce previous warp's 256 samples ====
    // (redundant per warp, but fully parallel: no intra-CTA barrier needed)
    float ha = 1.0f, hb = 0.0f;
    {
        const int hs0 = s0 - SPW;
        if (hs0 >= 0 && hs0 + CH <= NSAMP) {
            const int hv = hs0 >> 2;
            float4 x0 = ntv[hv], x1 = ntv[hv + 1];
            float y;
            y = CUTOFF * x0.x;
            y = fmaf(OMC, y, CUTOFF * x0.y);
            y = fmaf(OMC, y, CUTOFF * x0.z);
            y = fmaf(OMC, y, CUTOFF * x0.w);
            y = fmaf(OMC, y, CUTOFF * x1.x);
            y = fmaf(OMC, y, CUTOFF * x1.y);
            y = fmaf(OMC, y, CUTOFF * x1.z);
            y = fmaf(OMC, y, CUTOFF * x1.w);
            hb = y; ha = A8;
        }
    }
    #pragma unroll
    for (int off = 1; off < 32; off <<= 1) {
        float au = __shfl_up_sync(0xffffffffu, ha, off);
        float bu = __shfl_up_sync(0xffffffffu, hb, off);
        if (lane >= off) { hb = fmaf(ha, bu, hb); ha *= au; }
    }
    const float y_warp = __shfl_sync(0xffffffffu, hb, 31);   // filter state at warp start

    // ======== Phase A2: main chunk partials from y=0 (register-resident) ========
    float bk[CH];
    float ma = 1.0f, mb = 0.0f;
    if (act) {
        float4 x0 = ntv[v0], x1 = ntv[v0 + 1];
        float xs[CH] = {x0.x, x0.y, x0.z, x0.w, x1.x, x1.y, x1.z, x1.w};
        float y = 0.0f;
        #pragma unroll
        for (int s = 0; s < CH; ++s) { y = fmaf(OMC, y, CUTOFF * xs[s]); bk[s] = y; }
        mb = y; ma = A8;
    }
    #pragma unroll
    for (int off = 1; off < 32; off <<= 1) {
        float au = __shfl_up_sync(0xffffffffu, ma, off);
        float bu = __shfl_up_sync(0xffffffffu, mb, off);
        if (lane >= off) { mb = fmaf(ma, bu, mb); ma *= au; }
    }
    float a_ie = __shfl_up_sync(0xffffffffu, ma, 1);
    float b_ie = __shfl_up_sync(0xffffffffu, mb, 1);
    if (lane == 0) { a_ie = 1.0f; b_ie = 0.0f; }
    const float y_in = fmaf(a_ie, y_warp, b_ie);

    // ======== Phase A3: transient via spiral/geometric recurrences ========
    float tr[CH];
    if (act) {
        const float t0 = (float)s0 * TSTEP;
        const float wf = 6.2831853f * freq_t;
        float sn, cs;
        sincosf(wf * t0, &sn, &cs);                 // accurate start phase
        const float sd = __sinf(wf * TSTEP);        // tiny-arg step rotation
        const float cd = __cosf(wf * TSTEP);
        const float m1 = __expf(-decay_t * TSTEP);
        const float m2 = __expf(-20.0f * decay_t * TSTEP);
        const float cdm = cd * m1, sdm = sd * m1;   // rotation x decay fused
        const float K  = gain_t * sat;
        const float e1 = __expf(-decay_t * t0);
        float u = sn * e1 * K;                       // = sn*e1*gain*sat (tanh arg)
        float v = cs * e1 * K;
        float e2g = __expf(-20.0f * decay_t * t0) * (gain_t * 0.5f);
        float q   = OMC * y_in * e2g;                // = 0.9^{s+1} * y_in * e2g_s
        const float cq = OMC * m2;
        #pragma unroll
        for (int s = 0; s < CH; ++s) {
            float sq = tanh_fast(u);                 // saturated sine
            tr[s] = sq + fmaf(bk[s], e2g, q);        // + filtered-noise component
            float u2 = fmaf(u, cdm,  v * sdm);       // spiral step
            float v2 = fmaf(v, cdm, -u * sdm);
            u = u2; v = v2;
            e2g *= m2; q *= cq;
        }
        float4* tv = (float4*)g_trans;
        tv[v0]     = make_float4(tr[0], tr[1], tr[2], tr[3]);
        tv[v0 + 1] = make_float4(tr[4], tr[5], tr[6], tr[7]);
    }

    // ---- prefetch noise_n (cold) + envelope setup: overlaps sync + staging ----
    float4 nn0 = make_float4(0.f, 0.f, 0.f, 0.f), nn1 = nn0;
    if (act) { nn0 = ((const float4*)noise_n)[v0]; nn1 = ((const float4*)noise_n)[v0 + 1]; }
    const float t0c = (float)s0 * TSTEP;
    float eA = __expf(-attack_n * t0c);
    float eD = __expf(-decay_n  * t0c);
    const float a1 = __expf(-attack_n * TSTEP);
    const float d1 = __expf(-decay_n  * TSTEP);

    // cluster barrier: arrive=release orders g_trans stores; wait=acquire.
    cluster_sync();

    // ======== Phase B: resonator, REDUNDANT per CTA, chains run from smem ========
    // Stage g_trans -> local smem (coalesced float4 burst, high MLP)
    {
        const float4* tv = (const float4*)g_trans;
        float4*       sv = (float4*)str;
        #pragma unroll
        for (int j = 0; j < 12; ++j) {
            int i4 = tid + j * NTHR;
            if (i4 < NSAMP / 4) sv[i4] = tv[i4];
        }
    }

    const float D  = 48000.0f / freq_r;
    const int   Di = (int)D;
    const bool fastp = (D >= 1.0f) && ((float)Di == D) && (Di < NSAMP);

    if (fastp) {
        __syncthreads();
        // Integer delay: frac == 0 exactly -> Di independent chains, LDS-fed.
        for (int r = tid; r < Di; r += NTHR) {
            float yv = str[r];            // i < D => valid==0 => out = transient
            sre[r] = yv;
            #pragma unroll 5
            for (int i = r + Di; i < NSAMP; i += Di) {
                yv = fmaf(feedback, yv, str[i]);
                sre[i] = yv;
            }
        }
        __syncthreads();
    } else {
        // Generic fractional delay: wave-synchronous over zeroed smem res.
        for (int i = tid; i < NSAMP; i += NTHR) sre[i] = 0.0f;
        __syncthreads();
        if (tid == 0) sre[0] = str[0];
        int cD = (int)ceilf(D);
        int W  = min(max(cD - 1, 1), NTHR);
        __syncthreads();
        for (int b0 = 1; b0 < NSAMP; b0 += W) {
            const int i = b0 + tid;
            if (tid < W && i < NSAMP) {
                float delayed = (float)i - D;
                float valid   = (delayed >= 0.0f) ? 1.0f : 0.0f;
                int fl = min(max((int)floorf(delayed), 0), NSAMP - 1);
                int ce = min(fl + 1, NSAMP - 1);
                float frac = delayed - (float)fl;   // after clamp, as in reference
                float interp = (1.0f - frac) * sre[fl] + frac * sre[ce];
                sre[i] = str[i] + feedback * interp * valid;
            }
            __syncthreads();
        }
    }

    // ======== Phase C: noise envelope + final sum (tr in regs, res in smem) ====
    if (act) {
        const float4* rv = (const float4*)sre;
        float4 rs0 = rv[v0], rs1 = rv[v0 + 1];
        const float nnf[CH] = {nn0.x, nn0.y, nn0.z, nn0.w, nn1.x, nn1.y, nn1.z, nn1.w};
        const float rsf[CH] = {rs0.x, rs0.y, rs0.z, rs0.w, rs1.x, rs1.y, rs1.z, rs1.w};
        float o[CH];
        float eAk = eA, eDk = eD;
        #pragma unroll
        for (int s = 0; s < CH; ++s) {
            float env = (1.0f - eAk) * eDk;
            o[s] = fmaf(nnf[s] * gain_n, env, fmaf(rsf[s], gain_r, tr[s]));
            eAk *= a1; eDk *= d1;
        }
        float4* ov = (float4*)out;
        ov[v0]     = make_float4(o[0], o[1], o[2], o[3]);
        ov[v0 + 1] = make_float4(o[4], o[5], o[6], o[7]);
    }
}

extern "C" void kernel_launch(void* const* d_in, const int* in_sizes, int n_in,
                              void* d_out, int out_size)
{
    const float* params  = (const float*)d_in[0];
    const float* noise_t = (const float*)d_in[1];
    const float* noise_n = (const float*)d_in[2];
    float* out = (float*)d_out;

    const size_t smem_bytes = 2u * NSAMP * sizeof(float);   // 192000 B
    cudaFuncSetAttribute(drum_synth_cluster,
                         cudaFuncAttributeMaxDynamicSharedMemorySize,
                         (int)smem_bytes);

    drum_synth_cluster<<<NCTA, NTHR, smem_bytes>>>(params, noise_t, noise_n, out);
}